// round 13
// baseline (speedup 1.0000x reference)
#include <cuda_runtime.h>
#include <cuda_bf16.h>
#include <cstdint>

#define BATCH 8192
#define IND   128
#define HID   1024
#define OUTD  128
#define MB    32             // rows per CTA -> 256 CTAs (2/SM, one wave)
#define THREADS 384          // 8 MMA warps + 4 sweep warps
#define NSEG  9

#define CH_BYTES 20480
#define TRANS_OFF 81920
#define TP 34
#define MBAR_OFF 99328
#define SMEM_TOTAL 99392

#define ID_TR 2
#define ID_SR 3
#define BAR_MMA()      asm volatile("bar.sync 4, 256;" ::: "memory")
#define BAR_SYNC(id)   asm volatile("bar.sync %0, 384;"   :: "r"(id) : "memory")
#define BAR_ARRIVE(id) asm volatile("bar.arrive %0, 384;" :: "r"(id) : "memory")

typedef unsigned long long ull;

// ---- global scratch: packed, pre-swizzled chunk layouts ----
__device__ __align__(256) __nv_bfloat16 g_Spk[(size_t)256 * 36 * 2048];
__device__ __align__(256) __nv_bfloat16 g_Wpk[(size_t)8 * 36 * 8192];
__device__ __align__(256) __nv_bfloat16 g_WOpk[(size_t)36 * 8192];
__device__ __align__(256) float         g_diagT[8 * 128 * 128];   // [seg][i][c]
__device__ __align__(256) float         g_diagMicro[8 * 32 * 8];  // [seg][ib][8]

__device__ __forceinline__ uint32_t smem_u32(const void* p) {
    uint32_t a;
    asm("{ .reg .u64 t; cvta.to.shared.u64 t, %1; cvt.u32.u64 %0, t; }" : "=r"(a) : "l"(p));
    return a;
}
__device__ __forceinline__ ull ffma2(ull a, ull b, ull c) {
    ull d; asm("fma.rn.f32x2 %0, %1, %2, %3;" : "=l"(d) : "l"(a), "l"(b), "l"(c)); return d;
}
__device__ __forceinline__ ull dup2(float x) {
    ull d; asm("mov.b64 %0, {%1, %1};" : "=l"(d) : "f"(x)); return d;
}
__device__ __forceinline__ ull pack2(float x, float y) {
    ull d; asm("mov.b64 %0, {%1, %2};" : "=l"(d) : "f"(x), "f"(y)); return d;
}
__device__ __forceinline__ float2 unpack2(ull v) {
    float2 f; asm("mov.b64 {%0, %1}, %2;" : "=f"(f.x), "=f"(f.y) : "l"(v)); return f;
}
__device__ __forceinline__ float fast_tanh(float x) {
    float e; asm("ex2.approx.f32 %0, %1;" : "=f"(e) : "f"(x * 2.8853900817779268f));
    float r; asm("rcp.approx.f32 %0, %1;" : "=f"(r) : "f"(e + 1.0f));
    return fmaf(-2.0f, r, 1.0f);
}
__device__ __forceinline__ void ldmx4(uint32_t r[4], uint32_t a) {
    asm volatile("ldmatrix.sync.aligned.m8n8.x4.shared.b16 {%0,%1,%2,%3}, [%4];"
        : "=r"(r[0]), "=r"(r[1]), "=r"(r[2]), "=r"(r[3]) : "r"(a));
}
__device__ __forceinline__ void mma16816(float c[4], const uint32_t a[4],
                                         uint32_t b0, uint32_t b1) {
    asm volatile("mma.sync.aligned.m16n8k16.row.col.f32.bf16.bf16.f32 "
        "{%0,%1,%2,%3}, {%4,%5,%6,%7}, {%8,%9}, {%0,%1,%2,%3};"
        : "+f"(c[0]), "+f"(c[1]), "+f"(c[2]), "+f"(c[3])
        : "r"(a[0]), "r"(a[1]), "r"(a[2]), "r"(a[3]), "r"(b0), "r"(b1));
}

#define MBAR_INIT(a, n) \
    asm volatile("mbarrier.init.shared.b64 [%0], %1;" :: "r"(a), "r"((uint32_t)(n)) : "memory")

#define MBAR_WAIT(a, ph) do {                                                        \
    uint32_t _m = (a), _p = (ph), _d;                                                \
    asm volatile("{ .reg .pred p; mbarrier.try_wait.parity.acquire.cta.shared::cta.b64 p, [%1], %2; selp.b32 %0,1,0,p; }" \
        : "=r"(_d) : "r"(_m), "r"(_p) : "memory");                                   \
    if (!_d) {                                                                       \
        asm volatile("{ .reg .pred P1; WL_%=: mbarrier.try_wait.parity.acquire.cta.shared::cta.b64 P1, [%0], %1, 0x989680; @P1 bra.uni WD_%=; bra.uni WL_%=; WD_%=: }" \
            :: "r"(_m), "r"(_p) : "memory");                                         \
    }                                                                                \
} while (0)

// ======== prologue: split + pack + swizzle ========
#define R1 (BATCH * IND)
#define R2 (8 * 36 * 4096)
#define R3 (36 * 4096)
#define R4 (8 * 128 * 128)
#define R5 (8 * 32 * 8)

__global__ void split_kernel(const float* __restrict__ u,  const float* __restrict__ Bw,
                             const float* __restrict__ Bs, const float* __restrict__ Ds,
                             const float* __restrict__ Dw) {
    int idx = blockIdx.x * blockDim.x + threadIdx.x;
    if (idx < R1) {
        int r = idx >> 7, k = idx & 127;
        float v = u[idx];
        __nv_bfloat16 hi = __float2bfloat16_rn(v);
        __nv_bfloat16 lo = __float2bfloat16_rn(v - __bfloat162float(hi));
        int blk = r >> 5, rr = r & 31, kc = k >> 5, kk = k & 31;
        size_t base = ((size_t)(blk * 36 + kc)) * 4096 + (size_t)rr * 64
                    + 16 * ((kk >> 3) ^ ((rr >> 1) & 3)) + (kk & 7) * 2;
        *(__nv_bfloat16*)((char*)g_Spk + base)        = hi;
        *(__nv_bfloat16*)((char*)g_Spk + base + 2048) = lo;
    } else if (idx < R1 + R2) {
        int e = idx - R1;
        int kk = e & 31, n = (e >> 5) & 127, t = e >> 12;
        int kc = t % 36, seg = t / 36;
        int col = kc * 32 + kk, row = seg * 128 + n;
        float v = (col < 128) ? Bw[row * 128 + col] : Bs[(size_t)row * 1024 + col - 128];
        __nv_bfloat16 hi = __float2bfloat16_rn(v);
        __nv_bfloat16 lo = __float2bfloat16_rn(v - __bfloat162float(hi));
        size_t base = ((size_t)(seg * 36 + kc)) * 16384 + (size_t)n * 64
                    + 16 * ((kk >> 3) ^ ((n >> 1) & 3)) + (kk & 7) * 2;
        *(__nv_bfloat16*)((char*)g_Wpk + base)        = hi;
        *(__nv_bfloat16*)((char*)g_Wpk + base + 8192) = lo;
    } else if (idx < R1 + R2 + R3) {
        int e = idx - R1 - R2;
        int kk = e & 31, n = (e >> 5) & 127, kc = e >> 12;
        int col = kc * 32 + kk;
        float v = (col < 128) ? Dw[n * 128 + col] : Ds[(size_t)n * 1024 + col - 128];
        __nv_bfloat16 hi = __float2bfloat16_rn(v);
        __nv_bfloat16 lo = __float2bfloat16_rn(v - __bfloat162float(hi));
        size_t base = (size_t)kc * 16384 + (size_t)n * 64
                    + 16 * ((kk >> 3) ^ ((n >> 1) & 3)) + (kk & 7) * 2;
        *(__nv_bfloat16*)((char*)g_WOpk + base)        = hi;
        *(__nv_bfloat16*)((char*)g_WOpk + base + 8192) = lo;
    } else if (idx < R1 + R2 + R3 + R4) {
        int i4 = idx - R1 - R2 - R3;
        int seg = i4 >> 14, r = (i4 >> 7) & 127, c = i4 & 127;
        g_diagT[i4] = Bs[(size_t)(seg * 128 + c) * HID + seg * 128 + r];
    } else if (idx < R1 + R2 + R3 + R4 + R5) {
        int e = idx - R1 - R2 - R3 - R4;
        int seg = e >> 8, ib = (e >> 3) & 31, j = e & 7;
        const int qt[8] = {0,0,1,0,1,2,0,0};
        const int pt[8] = {1,2,2,3,3,3,0,0};
        float v = 0.f;
        if (j < 6) {
            int q = qt[j], p = pt[j];
            v = Bs[(size_t)(seg * 128 + 4 * ib + p) * HID + seg * 128 + 4 * ib + q];
        }
        g_diagMicro[e] = v;
    }
}

// stage one chunk: 2 bulk copies + expect_tx, single thread (tid==128 = MMA warp 4 lane 0)
__device__ __forceinline__ void stage_bulk(uint32_t sb, int blk, int seg, int kc,
                                           int absidx, int tid) {
    if (tid != 128) return;
    uint32_t mb  = sb + MBAR_OFF + 8u * (uint32_t)(absidx & 3);
    uint32_t dst = sb + (uint32_t)(absidx & 3) * CH_BYTES;
    const char* Asrc = (const char*)g_Spk + ((size_t)blk * 36 + kc) * 4096;
    const char* Bsrc = (seg < 8)
        ? (const char*)g_Wpk + ((size_t)seg * 36 + kc) * 16384
        : (const char*)g_WOpk + (size_t)kc * 16384;
    asm volatile("mbarrier.arrive.expect_tx.shared.b64 _, [%0], %1;"
                 :: "r"(mb), "r"(20480u) : "memory");
    asm volatile("cp.async.bulk.shared::cta.global.mbarrier::complete_tx::bytes [%0], [%1], %2, [%3];"
                 :: "r"(dst), "l"(Asrc), "r"(4096u), "r"(mb) : "memory");
    asm volatile("cp.async.bulk.shared::cta.global.mbarrier::complete_tx::bytes [%0], [%1], %2, [%3];"
                 :: "r"(dst + 4096u), "l"(Bsrc), "r"(16384u), "r"(mb) : "memory");
}

// ======== main fused kernel: 8 MMA warps + 4 sweep warps ========
__global__ void __launch_bounds__(THREADS, 2)
ren_main(float* __restrict__ out)
{
    extern __shared__ char smem[];
    const uint32_t sb = smem_u32(smem);
    float* trans = (float*)(smem + TRANS_OFF);

    const int tid  = threadIdx.x;
    const int wid  = tid >> 5;
    const int lane = tid & 31;
    const int blk  = blockIdx.x;
    const int row0 = blk * MB;

    if (tid < 4) MBAR_INIT(sb + MBAR_OFF + 8 * tid, 1);
    __syncthreads();

    if (wid >= 4) {
        // ================= MMA group (warps 4..11, 16x32 tiles) =================
        const int m  = wid - 4;          // 0..7
        const int wr = m & 1;            // 16-row strip
        const int wc = m >> 1;           // 32-col strip (0..3)
        const int l15 = lane & 15;
        const uint32_t rowA = (uint32_t)(16 * wr + l15) * 64;
        const uint32_t rowB = (uint32_t)(32 * wc + l15) * 64;
        const int swzr  = (l15 >> 1) & 3;
        const int khalf = lane >> 4;
        uint32_t offk[2];
        offk[0] = (uint32_t)((khalf)     ^ swzr) << 4;
        offk[1] = (uint32_t)((2 + khalf) ^ swzr) << 4;
        const int r_in = lane >> 2;
        const int cp2  = (lane & 3) << 1;

        stage_bulk(sb, blk, 0, 0, 0, tid);
        stage_bulk(sb, blk, 0, 1, 1, tid);
        stage_bulk(sb, blk, 0, 2, 2, tid);

        int absb = 0;
        for (int seg = 0; seg < NSEG; ++seg) {
            const bool isOut = (seg == 8);
            const int  NC = isOut ? 36 : (4 * (seg + 1));

            float acc[4][4];
            #pragma unroll
            for (int a = 0; a < 4; ++a)
                #pragma unroll
                for (int c = 0; c < 4; ++c) acc[a][c] = 0.f;

            for (int ci = 0; ci < NC; ++ci) {
                const int a = absb + ci;
                MBAR_WAIT(sb + MBAR_OFF + 8u * (uint32_t)(a & 3), (uint32_t)((a >> 2) & 1));
                BAR_MMA();
                if (ci + 3 < NC) {
                    if (seg >= 1 && ci + 3 == 4 * seg) BAR_SYNC(ID_SR);
                    stage_bulk(sb, blk, seg, ci + 3, a + 3, tid);
                }

                const uint32_t bufb = sb + (uint32_t)(a & 3) * CH_BYTES;
                const uint32_t aHi = bufb + rowA;
                const uint32_t aLo = bufb + 2048 + rowA;
                const uint32_t bHi = bufb + 4096 + rowB;
                const uint32_t bLo = bufb + 12288 + rowB;

                #pragma unroll
                for (int ks = 0; ks < 2; ++ks) {
                    const uint32_t ok = offk[ks];
                    uint32_t aH[4], aL[4];
                    ldmx4(aH, aHi + ok);
                    ldmx4(aL, aLo + ok);
                    #pragma unroll
                    for (int nb = 0; nb < 2; ++nb) {
                        uint32_t bh[4], bl[4];
                        ldmx4(bh, bHi + nb * 1024 + ok);
                        ldmx4(bl, bLo + nb * 1024 + ok);
                        mma16816(acc[2*nb],   aH, bh[0], bh[2]);
                        mma16816(acc[2*nb+1], aH, bh[1], bh[3]);
                        mma16816(acc[2*nb],   aH, bl[0], bl[2]);
                        mma16816(acc[2*nb+1], aH, bl[1], bl[3]);
                        mma16816(acc[2*nb],   aL, bh[0], bh[2]);
                        mma16816(acc[2*nb+1], aL, bh[1], bh[3]);
                    }
                }
            }
            BAR_MMA();

            if (isOut) {
                #pragma unroll
                for (int nf = 0; nf < 4; ++nf) {
                    const int row = 16 * wr + r_in;
                    const int col = 32 * wc + 8 * nf + cp2;
                    *(float2*)(out + (size_t)(row0 + row) * OUTD + col) =
                        make_float2(acc[nf][0], acc[nf][1]);
                    *(float2*)(out + (size_t)(row0 + row + 8) * OUTD + col) =
                        make_float2(acc[nf][2], acc[nf][3]);
                }
            } else {
                #pragma unroll
                for (int nf = 0; nf < 4; ++nf) {
                    const int rowb = 16 * wr + r_in;
                    const int colb = 32 * wc + 8 * nf + cp2;
                    trans[(colb    ) * TP + rowb    ] = acc[nf][0];
                    trans[(colb + 1) * TP + rowb    ] = acc[nf][1];
                    trans[(colb    ) * TP + rowb + 8] = acc[nf][2];
                    trans[(colb + 1) * TP + rowb + 8] = acc[nf][3];
                }
                asm volatile("membar.cta;" ::: "memory");
                BAR_ARRIVE(ID_TR);

                absb += NC;
                stage_bulk(sb, blk, seg + 1, 0, absb + 0, tid);
                stage_bulk(sb, blk, seg + 1, 1, absb + 1, tid);
                stage_bulk(sb, blk, seg + 1, 2, absb + 2, tid);
                absb -= NC;
            }
            absb += NC;
        }
    } else {
        // ========== sweep group (warps 0..3): batched 4-step micro-solve ==========
        const int w = wid;
        const int cbase = 4 * lane;
        const int rr_sw = 8 * w + lane;      // valid for lane<8

        for (int seg = 0; seg < 8; ++seg) {
            BAR_SYNC(ID_TR);

            ull a2[4][4];
            #pragma unroll
            for (int q = 0; q < 4; ++q) {
                const float* tp = trans + (4 * lane + q) * TP + 8 * w;
                #pragma unroll
                for (int h = 0; h < 4; ++h) {
                    float2 v = *(const float2*)(tp + 2 * h);
                    a2[q][h] = pack2(v.x, v.y);
                }
            }

            const float* dT = g_diagT + seg * 16384;
            const float* dM = g_diagMicro + seg * 256;
            float4 bmA = *(const float4*)(dM);
            float4 bmB = *(const float4*)(dM + 4);

            for (int ib = 0; ib < 32; ++ib) {
                float4 bq[4];
                #pragma unroll
                for (int q = 0; q < 4; ++q)
                    bq[q] = *(const float4*)(dT + (4 * ib + q) * 128 + cbase);

                float x0, x1, x2, x3;
                {
                    float xs[4];
                    #pragma unroll
                    for (int q = 0; q < 4; ++q) {
                        ull g0 = __shfl_sync(0xffffffffu, a2[q][0], ib);
                        ull g1 = __shfl_sync(0xffffffffu, a2[q][1], ib);
                        ull g2 = __shfl_sync(0xffffffffu, a2[q][2], ib);
                        ull g3 = __shfl_sync(0xffffffffu, a2[q][3], ib);
                        ull ga = (lane & 2) ? g1 : g0;
                        ull gb = (lane & 2) ? g3 : g2;
                        float2 pp = unpack2((lane & 4) ? gb : ga);
                        xs[q] = (lane & 1) ? pp.y : pp.x;
                    }
                    x0 = xs[0]; x1 = xs[1]; x2 = xs[2]; x3 = xs[3];
                }
                const float b10 = bmA.x, b20 = bmA.y, b21 = bmA.z;
                const float b30 = bmA.w, b31 = bmB.x, b32 = bmB.y;
                if (ib < 31) {
                    bmA = *(const float4*)(dM + 8 * (ib + 1));
                    bmB = *(const float4*)(dM + 8 * (ib + 1) + 4);
                }

                float t0 = fast_tanh(x0);
                float y1 = fmaf(b10, t0, x1);
                float t1 = fast_tanh(y1);
                float y2 = fmaf(b21, t1, fmaf(b20, t0, x2));
                float t2 = fast_tanh(y2);
                float y3 = fmaf(b32, t2, fmaf(b31, t1, fmaf(b30, t0, x3)));
                float t3 = fast_tanh(y3);

                if (lane < 8) {
                    ull hiacc = 0, loacc = 0;
                    float tv[4] = {t0, t1, t2, t3};
                    #pragma unroll
                    for (int q = 0; q < 4; ++q) {
                        __nv_bfloat16 hb = __float2bfloat16_rn(tv[q]);
                        __nv_bfloat16 lb = __float2bfloat16_rn(tv[q] - __bfloat162float(hb));
                        unsigned short hs = *reinterpret_cast<unsigned short*>(&hb);
                        unsigned short ls = *reinterpret_cast<unsigned short*>(&lb);
                        hiacc |= (ull)hs << (16 * q);
                        loacc |= (ull)ls << (16 * q);
                    }
                    const int i0  = 4 * ib;
                    const int kc  = 4 * seg + 4 + (i0 >> 5);
                    const int kk0 = i0 & 31;
                    size_t base = ((size_t)(blk * 36 + kc)) * 4096 + (size_t)rr_sw * 64
                                + 16 * ((kk0 >> 3) ^ ((rr_sw >> 1) & 3)) + (kk0 & 7) * 2;
                    *(ull*)((char*)g_Spk + base)        = hiacc;
                    *(ull*)((char*)g_Spk + base + 2048) = loacc;
                }

                if (ib < 31) {
                    const bool act = (lane > ib);
                    float tq[4] = {t0, t1, t2, t3};
                    #pragma unroll
                    for (int q = 0; q < 4; ++q) {
                        float tp_ = __shfl_xor_sync(0xffffffffu, tq[q], 1);
                        ull u = pack2(tq[q], tp_);
                        ull S0 = __shfl_sync(0xffffffffu, u, 0);
                        ull S1 = __shfl_sync(0xffffffffu, u, 2);
                        ull S2 = __shfl_sync(0xffffffffu, u, 4);
                        ull S3 = __shfl_sync(0xffffffffu, u, 6);
                        if (act) {
                            ull b0 = dup2(bq[q].x), b1 = dup2(bq[q].y);
                            ull b2 = dup2(bq[q].z), b3 = dup2(bq[q].w);
                            a2[0][0] = ffma2(S0, b0, a2[0][0]);
                            a2[0][1] = ffma2(S1, b0, a2[0][1]);
                            a2[0][2] = ffma2(S2, b0, a2[0][2]);
                            a2[0][3] = ffma2(S3, b0, a2[0][3]);
                            a2[1][0] = ffma2(S0, b1, a2[1][0]);
                            a2[1][1] = ffma2(S1, b1, a2[1][1]);
                            a2[1][2] = ffma2(S2, b1, a2[1][2]);
                            a2[1][3] = ffma2(S3, b1, a2[1][3]);
                            a2[2][0] = ffma2(S0, b2, a2[2][0]);
                            a2[2][1] = ffma2(S1, b2, a2[2][1]);
                            a2[2][2] = ffma2(S2, b2, a2[2][2]);
                            a2[2][3] = ffma2(S3, b2, a2[2][3]);
                            a2[3][0] = ffma2(S0, b3, a2[3][0]);
                            a2[3][1] = ffma2(S1, b3, a2[3][1]);
                            a2[3][2] = ffma2(S2, b3, a2[3][2]);
                            a2[3][3] = ffma2(S3, b3, a2[3][3]);
                        }
                    }
                }
            }
            __threadfence();
            BAR_ARRIVE(ID_SR);
        }
    }
}

extern "C" void kernel_launch(void* const* d_in, const int* in_sizes, int n_in,
                              void* d_out, int out_size)
{
    const float* u  = (const float*)d_in[0];  // [8192,128]
    const float* Bw = (const float*)d_in[1];  // [1024,128]
    const float* Bs = (const float*)d_in[2];  // [1024,1024]
    const float* Ds = (const float*)d_in[3];  // [128,1024]
    const float* Dw = (const float*)d_in[4];  // [128,128]

    const int NTOT = R1 + R2 + R3 + R4 + R5;
    split_kernel<<<(NTOT + 255) / 256, 256>>>(u, Bw, Bs, Ds, Dw);

    cudaFuncSetAttribute(ren_main, cudaFuncAttributeMaxDynamicSharedMemorySize, SMEM_TOTAL);
    ren_main<<<BATCH / MB, THREADS, SMEM_TOTAL>>>((float*)d_out);
}

// round 14
// speedup vs baseline: 1.0915x; 1.0915x over previous
#include <cuda_runtime.h>
#include <cuda_bf16.h>
#include <cstdint>

#define BATCH 8192
#define IND   128
#define HID   1024
#define OUTD  128
#define MB    32             // rows per CTA -> 256 CTAs (2/SM, one wave)
#define THREADS 256
#define NSEG  9

#define CH_BYTES 40960       // K=64 chunk: A 8KB (hi/lo x2 kc32) + B 32KB
#define TRANS_OFF 81920      // 2 buffers before this
#define TP 34
#define MBAR_OFF 99328
#define SMEM_TOTAL 99392

#define ID_TR 2
#define ID_SR 3
#define BAR_MMA()      asm volatile("bar.sync 4, 128;" ::: "memory")
#define BAR_SYNC(id)   asm volatile("bar.sync %0, 256;"   :: "r"(id) : "memory")
#define BAR_ARRIVE(id) asm volatile("bar.arrive %0, 256;" :: "r"(id) : "memory")

typedef unsigned long long ull;

// ---- global scratch: packed, pre-swizzled chunk layouts (per kc32 block) ----
__device__ __align__(256) __nv_bfloat16 g_Spk[(size_t)256 * 36 * 2048];
__device__ __align__(256) __nv_bfloat16 g_Wpk[(size_t)8 * 36 * 8192];
__device__ __align__(256) __nv_bfloat16 g_WOpk[(size_t)36 * 8192];
__device__ __align__(256) float         g_diagT[8 * 128 * 128];   // [seg][i][c]
__device__ __align__(256) float         g_diagMicro[8 * 32 * 8];  // [seg][ib][8]

__device__ __forceinline__ uint32_t smem_u32(const void* p) {
    uint32_t a;
    asm("{ .reg .u64 t; cvta.to.shared.u64 t, %1; cvt.u32.u64 %0, t; }" : "=r"(a) : "l"(p));
    return a;
}
__device__ __forceinline__ ull ffma2(ull a, ull b, ull c) {
    ull d; asm("fma.rn.f32x2 %0, %1, %2, %3;" : "=l"(d) : "l"(a), "l"(b), "l"(c)); return d;
}
__device__ __forceinline__ ull dup2(float x) {
    ull d; asm("mov.b64 %0, {%1, %1};" : "=l"(d) : "f"(x)); return d;
}
__device__ __forceinline__ ull pack2(float x, float y) {
    ull d; asm("mov.b64 %0, {%1, %2};" : "=l"(d) : "f"(x), "f"(y)); return d;
}
__device__ __forceinline__ float2 unpack2(ull v) {
    float2 f; asm("mov.b64 {%0, %1}, %2;" : "=f"(f.x), "=f"(f.y) : "l"(v)); return f;
}
__device__ __forceinline__ float fast_tanh(float x) {
    float e; asm("ex2.approx.f32 %0, %1;" : "=f"(e) : "f"(x * 2.8853900817779268f));
    float r; asm("rcp.approx.f32 %0, %1;" : "=f"(r) : "f"(e + 1.0f));
    return fmaf(-2.0f, r, 1.0f);
}
__device__ __forceinline__ void ldmx4(uint32_t r[4], uint32_t a) {
    asm volatile("ldmatrix.sync.aligned.m8n8.x4.shared.b16 {%0,%1,%2,%3}, [%4];"
        : "=r"(r[0]), "=r"(r[1]), "=r"(r[2]), "=r"(r[3]) : "r"(a));
}
__device__ __forceinline__ void mma16816(float c[4], const uint32_t a[4],
                                         uint32_t b0, uint32_t b1) {
    asm volatile("mma.sync.aligned.m16n8k16.row.col.f32.bf16.bf16.f32 "
        "{%0,%1,%2,%3}, {%4,%5,%6,%7}, {%8,%9}, {%0,%1,%2,%3};"
        : "+f"(c[0]), "+f"(c[1]), "+f"(c[2]), "+f"(c[3])
        : "r"(a[0]), "r"(a[1]), "r"(a[2]), "r"(a[3]), "r"(b0), "r"(b1));
}

#define MBAR_INIT(a, n) \
    asm volatile("mbarrier.init.shared.b64 [%0], %1;" :: "r"(a), "r"((uint32_t)(n)) : "memory")

#define MBAR_WAIT(a, ph) do {                                                        \
    uint32_t _m = (a), _p = (ph), _d;                                                \
    asm volatile("{ .reg .pred p; mbarrier.try_wait.parity.acquire.cta.shared::cta.b64 p, [%1], %2; selp.b32 %0,1,0,p; }" \
        : "=r"(_d) : "r"(_m), "r"(_p) : "memory");                                   \
    if (!_d) {                                                                       \
        asm volatile("{ .reg .pred P1; WL_%=: mbarrier.try_wait.parity.acquire.cta.shared::cta.b64 P1, [%0], %1, 0x989680; @P1 bra.uni WD_%=; bra.uni WL_%=; WD_%=: }" \
            :: "r"(_m), "r"(_p) : "memory");                                         \
    }                                                                                \
} while (0)

// ======== prologue: split + pack + swizzle (unchanged layouts) ========
#define R1 (BATCH * IND)
#define R2 (8 * 36 * 4096)
#define R3 (36 * 4096)
#define R4 (8 * 128 * 128)
#define R5 (8 * 32 * 8)

__global__ void split_kernel(const float* __restrict__ u,  const float* __restrict__ Bw,
                             const float* __restrict__ Bs, const float* __restrict__ Ds,
                             const float* __restrict__ Dw) {
    int idx = blockIdx.x * blockDim.x + threadIdx.x;
    if (idx < R1) {
        int r = idx >> 7, k = idx & 127;
        float v = u[idx];
        __nv_bfloat16 hi = __float2bfloat16_rn(v);
        __nv_bfloat16 lo = __float2bfloat16_rn(v - __bfloat162float(hi));
        int blk = r >> 5, rr = r & 31, kc = k >> 5, kk = k & 31;
        size_t base = ((size_t)(blk * 36 + kc)) * 4096 + (size_t)rr * 64
                    + 16 * ((kk >> 3) ^ ((rr >> 1) & 3)) + (kk & 7) * 2;
        *(__nv_bfloat16*)((char*)g_Spk + base)        = hi;
        *(__nv_bfloat16*)((char*)g_Spk + base + 2048) = lo;
    } else if (idx < R1 + R2) {
        int e = idx - R1;
        int kk = e & 31, n = (e >> 5) & 127, t = e >> 12;
        int kc = t % 36, seg = t / 36;
        int col = kc * 32 + kk, row = seg * 128 + n;
        float v = (col < 128) ? Bw[row * 128 + col] : Bs[(size_t)row * 1024 + col - 128];
        __nv_bfloat16 hi = __float2bfloat16_rn(v);
        __nv_bfloat16 lo = __float2bfloat16_rn(v - __bfloat162float(hi));
        size_t base = ((size_t)(seg * 36 + kc)) * 16384 + (size_t)n * 64
                    + 16 * ((kk >> 3) ^ ((n >> 1) & 3)) + (kk & 7) * 2;
        *(__nv_bfloat16*)((char*)g_Wpk + base)        = hi;
        *(__nv_bfloat16*)((char*)g_Wpk + base + 8192) = lo;
    } else if (idx < R1 + R2 + R3) {
        int e = idx - R1 - R2;
        int kk = e & 31, n = (e >> 5) & 127, kc = e >> 12;
        int col = kc * 32 + kk;
        float v = (col < 128) ? Dw[n * 128 + col] : Ds[(size_t)n * 1024 + col - 128];
        __nv_bfloat16 hi = __float2bfloat16_rn(v);
        __nv_bfloat16 lo = __float2bfloat16_rn(v - __bfloat162float(hi));
        size_t base = (size_t)kc * 16384 + (size_t)n * 64
                    + 16 * ((kk >> 3) ^ ((n >> 1) & 3)) + (kk & 7) * 2;
        *(__nv_bfloat16*)((char*)g_WOpk + base)        = hi;
        *(__nv_bfloat16*)((char*)g_WOpk + base + 8192) = lo;
    } else if (idx < R1 + R2 + R3 + R4) {
        int i4 = idx - R1 - R2 - R3;
        int seg = i4 >> 14, r = (i4 >> 7) & 127, c = i4 & 127;
        g_diagT[i4] = Bs[(size_t)(seg * 128 + c) * HID + seg * 128 + r];
    } else if (idx < R1 + R2 + R3 + R4 + R5) {
        int e = idx - R1 - R2 - R3 - R4;
        int seg = e >> 8, ib = (e >> 3) & 31, j = e & 7;
        const int qt[8] = {0,0,1,0,1,2,0,0};
        const int pt[8] = {1,2,2,3,3,3,0,0};
        float v = 0.f;
        if (j < 6) {
            int q = qt[j], p = pt[j];
            v = Bs[(size_t)(seg * 128 + 4 * ib + p) * HID + seg * 128 + 4 * ib + q];
        }
        g_diagMicro[e] = v;
    }
}

// stage one K=64 chunk (two contiguous kc32 blocks): 2 bulk copies, single thread
__device__ __forceinline__ void stage_bulk(uint32_t sb, int blk, int seg, int kc64,
                                           int absidx, int tid) {
    if (tid != 128) return;
    uint32_t mb  = sb + MBAR_OFF + 8u * (uint32_t)(absidx & 1);
    uint32_t dst = sb + (uint32_t)(absidx & 1) * CH_BYTES;
    const int kc32 = kc64 * 2;
    const char* Asrc = (const char*)g_Spk + ((size_t)blk * 36 + kc32) * 4096;
    const char* Bsrc = (seg < 8)
        ? (const char*)g_Wpk + ((size_t)seg * 36 + kc32) * 16384
        : (const char*)g_WOpk + (size_t)kc32 * 16384;
    asm volatile("mbarrier.arrive.expect_tx.shared.b64 _, [%0], %1;"
                 :: "r"(mb), "r"(40960u) : "memory");
    asm volatile("cp.async.bulk.shared::cta.global.mbarrier::complete_tx::bytes [%0], [%1], %2, [%3];"
                 :: "r"(dst), "l"(Asrc), "r"(8192u), "r"(mb) : "memory");
    asm volatile("cp.async.bulk.shared::cta.global.mbarrier::complete_tx::bytes [%0], [%1], %2, [%3];"
                 :: "r"(dst + 8192u), "l"(Bsrc), "r"(32768u), "r"(mb) : "memory");
}

// ======== main fused kernel: warp-specialized, K=64 chunks ========
__global__ void __launch_bounds__(THREADS, 2)
ren_main(float* __restrict__ out)
{
    extern __shared__ char smem[];
    const uint32_t sb = smem_u32(smem);
    float* trans = (float*)(smem + TRANS_OFF);

    const int tid  = threadIdx.x;
    const int wid  = tid >> 5;
    const int lane = tid & 31;
    const int blk  = blockIdx.x;
    const int row0 = blk * MB;

    if (tid < 2) MBAR_INIT(sb + MBAR_OFF + 8 * tid, 1);
    __syncthreads();

    if (wid >= 4) {
        // ================= MMA group (warps 4..7, 16x64 tiles) =================
        const int m  = wid - 4;
        const int wr = m & 1;            // 16-row strip
        const int wc = m >> 1;           // 64-col strip
        const int l15 = lane & 15;
        const uint32_t rowA = (uint32_t)(16 * wr + l15) * 64;
        const uint32_t rowB = (uint32_t)(64 * wc + l15) * 64;
        const int swzr  = (l15 >> 1) & 3;
        const int khalf = lane >> 4;
        uint32_t offk[2];
        offk[0] = (uint32_t)((khalf)     ^ swzr) << 4;
        offk[1] = (uint32_t)((2 + khalf) ^ swzr) << 4;
        const int r_in = lane >> 2;
        const int cp2  = (lane & 3) << 1;

        stage_bulk(sb, blk, 0, 0, 0, tid);   // prime seg0 chunk 0

        int absb = 0;
        for (int seg = 0; seg < NSEG; ++seg) {
            const bool isOut = (seg == 8);
            const int  NC = 2 * (seg + 1);   // K=64 chunks (isOut: 18)

            float acc[8][4];
            #pragma unroll
            for (int a = 0; a < 8; ++a)
                #pragma unroll
                for (int c = 0; c < 4; ++c) acc[a][c] = 0.f;

            for (int ci = 0; ci < NC; ++ci) {
                const int a = absb + ci;
                if (wid == 4)
                    MBAR_WAIT(sb + MBAR_OFF + 8u * (uint32_t)(a & 1), (uint32_t)((a >> 1) & 1));
                BAR_MMA();   // releases other warps; also fences buffer reuse
                if (ci + 1 < NC) {
                    if (seg >= 1 && ci + 1 == 2 * seg) BAR_SYNC(ID_SR);  // s(seg-1) ready
                    stage_bulk(sb, blk, seg, ci + 1, a + 1, tid);
                }

                const uint32_t bufb = sb + (uint32_t)(a & 1) * CH_BYTES;
                #pragma unroll
                for (int sub = 0; sub < 2; ++sub) {
                    const uint32_t aHi = bufb + sub * 4096 + rowA;
                    const uint32_t aLo = aHi + 2048;
                    const uint32_t bHi = bufb + 8192 + sub * 16384 + rowB;
                    const uint32_t bLo = bHi + 8192;
                    #pragma unroll
                    for (int ks = 0; ks < 2; ++ks) {
                        const uint32_t ok = offk[ks];
                        uint32_t aH[4], aL[4];
                        ldmx4(aH, aHi + ok);
                        ldmx4(aL, aLo + ok);
                        #pragma unroll
                        for (int nb = 0; nb < 4; ++nb) {
                            uint32_t bh[4], bl[4];
                            ldmx4(bh, bHi + nb * 1024 + ok);
                            ldmx4(bl, bLo + nb * 1024 + ok);
                            mma16816(acc[2*nb],   aH, bh[0], bh[2]);
                            mma16816(acc[2*nb+1], aH, bh[1], bh[3]);
                            mma16816(acc[2*nb],   aH, bl[0], bl[2]);
                            mma16816(acc[2*nb+1], aH, bl[1], bl[3]);
                            mma16816(acc[2*nb],   aL, bh[0], bh[2]);
                            mma16816(acc[2*nb+1], aL, bh[1], bh[3]);
                        }
                    }
                }
            }
            BAR_MMA();   // all MMA warps past last chunk's LDSMs

            if (isOut) {
                #pragma unroll
                for (int nf = 0; nf < 8; ++nf) {
                    const int row = 16 * wr + r_in;
                    const int col = 64 * wc + 8 * nf + cp2;
                    *(float2*)(out + (size_t)(row0 + row) * OUTD + col) =
                        make_float2(acc[nf][0], acc[nf][1]);
                    *(float2*)(out + (size_t)(row0 + row + 8) * OUTD + col) =
                        make_float2(acc[nf][2], acc[nf][3]);
                }
            } else {
                #pragma unroll
                for (int nf = 0; nf < 8; ++nf) {
                    const int rowb = 16 * wr + r_in;
                    const int colb = 64 * wc + 8 * nf + cp2;
                    trans[(colb    ) * TP + rowb    ] = acc[nf][0];
                    trans[(colb + 1) * TP + rowb    ] = acc[nf][1];
                    trans[(colb    ) * TP + rowb + 8] = acc[nf][2];
                    trans[(colb + 1) * TP + rowb + 8] = acc[nf][3];
                }
                asm volatile("membar.cta;" ::: "memory");
                BAR_ARRIVE(ID_TR);   // hand trans to sweep group

                // prime next segment's chunk 0 (u columns, s-independent)
                stage_bulk(sb, blk, seg + 1, 0, absb + NC, tid);
            }
            absb += NC;
        }
    } else {
        // ========== sweep group (warps 0..3): batched 4-step micro-solve ==========
        const int w = wid;
        const int cbase = 4 * lane;
        const int rr_sw = 8 * w + lane;      // valid for lane<8

        for (int seg = 0; seg < 8; ++seg) {
            BAR_SYNC(ID_TR);

            ull a2[4][4];
            #pragma unroll
            for (int q = 0; q < 4; ++q) {
                const float* tp = trans + (4 * lane + q) * TP + 8 * w;
                #pragma unroll
                for (int h = 0; h < 4; ++h) {
                    float2 v = *(const float2*)(tp + 2 * h);
                    a2[q][h] = pack2(v.x, v.y);
                }
            }

            const float* dT = g_diagT + seg * 16384;
            const float* dM = g_diagMicro + seg * 256;
            float4 bmA = *(const float4*)(dM);
            float4 bmB = *(const float4*)(dM + 4);

            for (int ib = 0; ib < 32; ++ib) {
                float4 bq[4];
                #pragma unroll
                for (int q = 0; q < 4; ++q)
                    bq[q] = *(const float4*)(dT + (4 * ib + q) * 128 + cbase);

                float x0, x1, x2, x3;
                {
                    float xs[4];
                    #pragma unroll
                    for (int q = 0; q < 4; ++q) {
                        ull g0 = __shfl_sync(0xffffffffu, a2[q][0], ib);
                        ull g1 = __shfl_sync(0xffffffffu, a2[q][1], ib);
                        ull g2 = __shfl_sync(0xffffffffu, a2[q][2], ib);
                        ull g3 = __shfl_sync(0xffffffffu, a2[q][3], ib);
                        ull ga = (lane & 2) ? g1 : g0;
                        ull gb = (lane & 2) ? g3 : g2;
                        float2 pp = unpack2((lane & 4) ? gb : ga);
                        xs[q] = (lane & 1) ? pp.y : pp.x;
                    }
                    x0 = xs[0]; x1 = xs[1]; x2 = xs[2]; x3 = xs[3];
                }
                const float b10 = bmA.x, b20 = bmA.y, b21 = bmA.z;
                const float b30 = bmA.w, b31 = bmB.x, b32 = bmB.y;
                if (ib < 31) {
                    bmA = *(const float4*)(dM + 8 * (ib + 1));
                    bmB = *(const float4*)(dM + 8 * (ib + 1) + 4);
                }

                float t0 = fast_tanh(x0);
                float y1 = fmaf(b10, t0, x1);
                float t1 = fast_tanh(y1);
                float y2 = fmaf(b21, t1, fmaf(b20, t0, x2));
                float t2 = fast_tanh(y2);
                float y3 = fmaf(b32, t2, fmaf(b31, t1, fmaf(b30, t0, x3)));
                float t3 = fast_tanh(y3);

                if (lane < 8) {
                    ull hiacc = 0, loacc = 0;
                    float tv[4] = {t0, t1, t2, t3};
                    #pragma unroll
                    for (int q = 0; q < 4; ++q) {
                        __nv_bfloat16 hb = __float2bfloat16_rn(tv[q]);
                        __nv_bfloat16 lb = __float2bfloat16_rn(tv[q] - __bfloat162float(hb));
                        unsigned short hs = *reinterpret_cast<unsigned short*>(&hb);
                        unsigned short ls = *reinterpret_cast<unsigned short*>(&lb);
                        hiacc |= (ull)hs << (16 * q);
                        loacc |= (ull)ls << (16 * q);
                    }
                    const int i0  = 4 * ib;
                    const int kc  = 4 * seg + 4 + (i0 >> 5);
                    const int kk0 = i0 & 31;
                    size_t base = ((size_t)(blk * 36 + kc)) * 4096 + (size_t)rr_sw * 64
                                + 16 * ((kk0 >> 3) ^ ((rr_sw >> 1) & 3)) + (kk0 & 7) * 2;
                    *(ull*)((char*)g_Spk + base)        = hiacc;
                    *(ull*)((char*)g_Spk + base + 2048) = loacc;
                }

                if (ib < 31) {
                    const bool act = (lane > ib);
                    float tq[4] = {t0, t1, t2, t3};
                    #pragma unroll
                    for (int q = 0; q < 4; ++q) {
                        float tp_ = __shfl_xor_sync(0xffffffffu, tq[q], 1);
                        ull u = pack2(tq[q], tp_);
                        ull S0 = __shfl_sync(0xffffffffu, u, 0);
                        ull S1 = __shfl_sync(0xffffffffu, u, 2);
                        ull S2 = __shfl_sync(0xffffffffu, u, 4);
                        ull S3 = __shfl_sync(0xffffffffu, u, 6);
                        if (act) {
                            ull b0 = dup2(bq[q].x), b1 = dup2(bq[q].y);
                            ull b2 = dup2(bq[q].z), b3 = dup2(bq[q].w);
                            a2[0][0] = ffma2(S0, b0, a2[0][0]);
                            a2[0][1] = ffma2(S1, b0, a2[0][1]);
                            a2[0][2] = ffma2(S2, b0, a2[0][2]);
                            a2[0][3] = ffma2(S3, b0, a2[0][3]);
                            a2[1][0] = ffma2(S0, b1, a2[1][0]);
                            a2[1][1] = ffma2(S1, b1, a2[1][1]);
                            a2[1][2] = ffma2(S2, b1, a2[1][2]);
                            a2[1][3] = ffma2(S3, b1, a2[1][3]);
                            a2[2][0] = ffma2(S0, b2, a2[2][0]);
                            a2[2][1] = ffma2(S1, b2, a2[2][1]);
                            a2[2][2] = ffma2(S2, b2, a2[2][2]);
                            a2[2][3] = ffma2(S3, b2, a2[2][3]);
                            a2[3][0] = ffma2(S0, b3, a2[3][0]);
                            a2[3][1] = ffma2(S1, b3, a2[3][1]);
                            a2[3][2] = ffma2(S2, b3, a2[3][2]);
                            a2[3][3] = ffma2(S3, b3, a2[3][3]);
                        }
                    }
                }
            }
            __threadfence();
            BAR_ARRIVE(ID_SR);
        }
    }
}

extern "C" void kernel_launch(void* const* d_in, const int* in_sizes, int n_in,
                              void* d_out, int out_size)
{
    const float* u  = (const float*)d_in[0];  // [8192,128]
    const float* Bw = (const float*)d_in[1];  // [1024,128]
    const float* Bs = (const float*)d_in[2];  // [1024,1024]
    const float* Ds = (const float*)d_in[3];  // [128,1024]
    const float* Dw = (const float*)d_in[4];  // [128,128]

    const int NTOT = R1 + R2 + R3 + R4 + R5;
    split_kernel<<<(NTOT + 255) / 256, 256>>>(u, Bw, Bs, Ds, Dw);

    cudaFuncSetAttribute(ren_main, cudaFuncAttributeMaxDynamicSharedMemorySize, SMEM_TOTAL);
    ren_main<<<BATCH / MB, THREADS, SMEM_TOTAL>>>((float*)d_out);
}